// round 1
// baseline (speedup 1.0000x reference)
#include <cuda_runtime.h>
#include <math.h>
#include <stdint.h>

#define N_NODES 100000
#define N_EDGES 1600000
#define D 128
#define NEG_SLOPE 0.01f

// ---------------- scratch (no allocations allowed) ----------------
__device__ float g_z[N_NODES * D];        // 51.2 MB
__device__ float g_ssrc[N_NODES];
__device__ float g_sdst[N_NODES];
__device__ int   g_deg[N_NODES];
__device__ int   g_off[N_NODES + 1];
__device__ int   g_cur[N_NODES];
__device__ int   g_csr_src[N_EDGES];      // src node id per CSR slot

// ---------------- GEMM: z = h @ W  (fp32 SIMT tiled) ----------------
// BM=64, BN=128, BK=32. 256 threads, each computes 4 rows x 8 cols.
#define BM 64
#define BK 32
#define HS_STRIDE 36   // pad; 36 floats = 144B, 16B aligned for float4 stores

__global__ __launch_bounds__(256) void gemm_kernel(const float* __restrict__ h,
                                                   const float* __restrict__ W) {
    __shared__ float hS[BM * HS_STRIDE];     // 64 x 32 (padded)
    __shared__ float wS[BK * D];             // 32 x 128

    const int t   = threadIdx.x;
    const int cx  = t & 15;          // 16 col groups of 8
    const int ry  = t >> 4;          // 16 row groups of 4
    const int row0 = blockIdx.x * BM;

    float acc[4][8];
    #pragma unroll
    for (int i = 0; i < 4; i++)
        #pragma unroll
        for (int j = 0; j < 8; j++) acc[i][j] = 0.0f;

    for (int k0 = 0; k0 < D; k0 += BK) {
        // load h tile: 64x32 floats = 512 float4, 2 per thread
        #pragma unroll
        for (int q = t; q < 512; q += 256) {
            int r  = q >> 3;               // 8 float4 per row
            int kc = (q & 7) << 2;
            int grow = row0 + r;
            float4 v = make_float4(0.f, 0.f, 0.f, 0.f);
            if (grow < N_NODES)
                v = *reinterpret_cast<const float4*>(&h[grow * D + k0 + kc]);
            *reinterpret_cast<float4*>(&hS[r * HS_STRIDE + kc]) = v;
        }
        // load W tile: 32x128 floats = 1024 float4, 4 per thread
        #pragma unroll
        for (int q = t; q < 1024; q += 256) {
            int r  = q >> 5;               // 32 float4 per row
            int jc = (q & 31) << 2;
            float4 v = *reinterpret_cast<const float4*>(&W[(k0 + r) * D + jc]);
            *reinterpret_cast<float4*>(&wS[r * D + jc]) = v;
        }
        __syncthreads();

        #pragma unroll
        for (int kk = 0; kk < BK; kk++) {
            float a[4];
            #pragma unroll
            for (int i = 0; i < 4; i++)
                a[i] = hS[(ry * 4 + i) * HS_STRIDE + kk];
            float4 b0 = *reinterpret_cast<const float4*>(&wS[kk * D + cx * 8]);
            float4 b1 = *reinterpret_cast<const float4*>(&wS[kk * D + cx * 8 + 4]);
            #pragma unroll
            for (int i = 0; i < 4; i++) {
                acc[i][0] += a[i] * b0.x;
                acc[i][1] += a[i] * b0.y;
                acc[i][2] += a[i] * b0.z;
                acc[i][3] += a[i] * b0.w;
                acc[i][4] += a[i] * b1.x;
                acc[i][5] += a[i] * b1.y;
                acc[i][6] += a[i] * b1.z;
                acc[i][7] += a[i] * b1.w;
            }
        }
        __syncthreads();
    }

    #pragma unroll
    for (int i = 0; i < 4; i++) {
        int grow = row0 + ry * 4 + i;
        if (grow < N_NODES) {
            float4 v0 = make_float4(acc[i][0], acc[i][1], acc[i][2], acc[i][3]);
            float4 v1 = make_float4(acc[i][4], acc[i][5], acc[i][6], acc[i][7]);
            *reinterpret_cast<float4*>(&g_z[grow * D + cx * 8])     = v0;
            *reinterpret_cast<float4*>(&g_z[grow * D + cx * 8 + 4]) = v1;
        }
    }
}

// ---------------- scores: s_src = z.a[:d], s_dst = z.a[d:] ----------------
__global__ __launch_bounds__(256) void scores_kernel(const float* __restrict__ attn) {
    int wid  = threadIdx.x >> 5;
    int lane = threadIdx.x & 31;
    int row  = blockIdx.x * 8 + wid;
    if (row >= N_NODES) return;

    float4 zv = *reinterpret_cast<const float4*>(&g_z[row * D + lane * 4]);
    float4 a1 = *reinterpret_cast<const float4*>(&attn[lane * 4]);
    float4 a2 = *reinterpret_cast<const float4*>(&attn[D + lane * 4]);

    float p1 = zv.x * a1.x + zv.y * a1.y + zv.z * a1.z + zv.w * a1.w;
    float p2 = zv.x * a2.x + zv.y * a2.y + zv.z * a2.z + zv.w * a2.w;
    #pragma unroll
    for (int o = 16; o > 0; o >>= 1) {
        p1 += __shfl_xor_sync(0xffffffffu, p1, o);
        p2 += __shfl_xor_sync(0xffffffffu, p2, o);
    }
    if (lane == 0) {
        g_ssrc[row] = p1;
        g_sdst[row] = p2;
    }
}

// ---------------- CSR build ----------------
__global__ void zero_deg_kernel() {
    int i = blockIdx.x * blockDim.x + threadIdx.x;
    if (i < N_NODES) g_deg[i] = 0;
}

__global__ void hist_kernel(const int* __restrict__ dst) {
    int i = blockIdx.x * blockDim.x + threadIdx.x;
    if (i < N_EDGES) atomicAdd(&g_deg[dst[i]], 1);
}

__global__ __launch_bounds__(1024) void scan_kernel() {
    __shared__ int wsum[32];
    __shared__ int carry_s;
    int t = threadIdx.x, lane = t & 31, wid = t >> 5;
    if (t == 0) carry_s = 0;
    __syncthreads();

    for (int base = 0; base < N_NODES; base += 1024) {
        int idx = base + t;
        int v = (idx < N_NODES) ? g_deg[idx] : 0;
        int x = v;
        #pragma unroll
        for (int o = 1; o < 32; o <<= 1) {
            int y = __shfl_up_sync(0xffffffffu, x, o);
            if (lane >= o) x += y;
        }
        if (lane == 31) wsum[wid] = x;
        __syncthreads();
        if (wid == 0) {
            int s = wsum[lane];
            #pragma unroll
            for (int o = 1; o < 32; o <<= 1) {
                int y = __shfl_up_sync(0xffffffffu, s, o);
                if (lane >= o) s += y;
            }
            wsum[lane] = s;
        }
        __syncthreads();
        int prefix = (wid > 0) ? wsum[wid - 1] : 0;
        int incl = x + prefix;
        int excl = incl - v;
        int carry = carry_s;
        if (idx < N_NODES) {
            g_off[idx] = carry + excl;
            g_cur[idx] = carry + excl;
        }
        __syncthreads();
        if (t == 1023) carry_s = carry + incl;
        __syncthreads();
    }
    if (t == 0) g_off[N_NODES] = carry_s;
}

__global__ void scatter_kernel(const int* __restrict__ src, const int* __restrict__ dst) {
    int i = blockIdx.x * blockDim.x + threadIdx.x;
    if (i < N_EDGES) {
        int d = dst[i];
        int p = atomicAdd(&g_cur[d], 1);
        g_csr_src[p] = src[i];
    }
}

// ---------------- fused softmax + weighted aggregation ----------------
// one warp per dst node; 128-float accumulator = float4 per lane
__global__ __launch_bounds__(128) void aggregate_kernel(float* __restrict__ out) {
    int wid  = threadIdx.x >> 5;
    int lane = threadIdx.x & 31;
    int n    = blockIdx.x * 4 + wid;
    if (n >= N_NODES) return;

    int start = g_off[n];
    int end   = g_off[n + 1];
    float sd  = g_sdst[n];

    // pass 1: segment max
    float m = -INFINITY;
    for (int i = start + lane; i < end; i += 32) {
        int s = g_csr_src[i];
        float e = g_ssrc[s] + sd;
        e = (e > 0.f) ? e : NEG_SLOPE * e;
        m = fmaxf(m, e);
    }
    #pragma unroll
    for (int o = 16; o > 0; o >>= 1)
        m = fmaxf(m, __shfl_xor_sync(0xffffffffu, m, o));

    // pass 2: denom
    float den = 0.f;
    for (int i = start + lane; i < end; i += 32) {
        int s = g_csr_src[i];
        float e = g_ssrc[s] + sd;
        e = (e > 0.f) ? e : NEG_SLOPE * e;
        den += __expf(e - m);
    }
    #pragma unroll
    for (int o = 16; o > 0; o >>= 1)
        den += __shfl_xor_sync(0xffffffffu, den, o);

    float inv = (end > start) ? (1.0f / den) : 0.f;

    // pass 3: all lanes walk every edge together; each lane owns 4 cols
    float4 acc = make_float4(0.f, 0.f, 0.f, 0.f);
    int col = lane * 4;
    for (int i = start; i < end; i++) {
        int s = g_csr_src[i];                       // broadcast load
        float e = g_ssrc[s] + sd;
        e = (e > 0.f) ? e : NEG_SLOPE * e;
        float w = __expf(e - m) * inv;
        float4 zv = *reinterpret_cast<const float4*>(&g_z[s * D + col]);
        acc.x += w * zv.x;
        acc.y += w * zv.y;
        acc.z += w * zv.z;
        acc.w += w * zv.w;
    }
    *reinterpret_cast<float4*>(&out[n * D + col]) = acc;
}

// ---------------- launch ----------------
extern "C" void kernel_launch(void* const* d_in, const int* in_sizes, int n_in,
                              void* d_out, int out_size) {
    const float* h    = (const float*)d_in[0];
    const float* W    = (const float*)d_in[1];
    const float* attn = (const float*)d_in[2];
    const int* esrc   = (const int*)d_in[3];
    const int* edst   = (const int*)d_in[4];
    float* out        = (float*)d_out;

    (void)in_sizes; (void)n_in; (void)out_size;

    gemm_kernel<<<(N_NODES + BM - 1) / BM, 256>>>(h, W);
    scores_kernel<<<(N_NODES + 7) / 8, 256>>>(attn);
    zero_deg_kernel<<<(N_NODES + 255) / 256, 256>>>();
    hist_kernel<<<(N_EDGES + 255) / 256, 256>>>(edst);
    scan_kernel<<<1, 1024>>>();
    scatter_kernel<<<(N_EDGES + 255) / 256, 256>>>(esrc, edst);
    aggregate_kernel<<<(N_NODES + 3) / 4, 128>>>(out);
}

// round 2
// speedup vs baseline: 1.5456x; 1.5456x over previous
#include <cuda_runtime.h>
#include <math.h>
#include <stdint.h>

#define N_NODES 100000
#define N_EDGES 1600000
#define D 128
#define NEG_SLOPE 0.01f
#define SCAN_BLKS ((N_NODES + 1023) / 1024)   // 98

// ---------------- scratch (no allocations allowed) ----------------
__device__ float g_z[N_NODES * D];        // 51.2 MB
__device__ float g_ssrc[N_NODES];
__device__ float g_sdst[N_NODES];
__device__ int   g_deg[N_NODES];
__device__ int   g_off[N_NODES + 1];
__device__ int   g_cur[N_NODES];
__device__ int   g_csr_src[N_EDGES];
__device__ int   g_bsum[128];
__device__ int   g_boff[128];

// ---------------- GEMM z = h@W with fused scores ----------------
// BM=128, BN=128 (full), BK=16. 256 threads, 8x8 per thread.
#define GBM 128
#define GBK 16
#define HT_STRIDE 132          // padded row stride for transposed h tile
// smem: phase A: hT[16][132] + wS[16][128];  phase B: sp1[128][17] + sp2[128][17]
#define SMEM_FLOATS 4352

__global__ __launch_bounds__(256) void gemm_scores_kernel(const float* __restrict__ h,
                                                          const float* __restrict__ W,
                                                          const float* __restrict__ attn) {
    __shared__ float smem[SMEM_FLOATS];
    float* hT = smem;                       // [GBK][HT_STRIDE]
    float* wS = smem + GBK * HT_STRIDE;     // [GBK][128]
    float* sp1 = smem;                      // [128][17] (reused)
    float* sp2 = smem + 128 * 17;

    const int t  = threadIdx.x;
    const int tx = t & 15;                  // col group (8 cols each)
    const int ty = t >> 4;                  // row group (8 rows each)
    const int row0 = blockIdx.x * GBM;

    float acc[8][8];
    #pragma unroll
    for (int i = 0; i < 8; i++)
        #pragma unroll
        for (int j = 0; j < 8; j++) acc[i][j] = 0.0f;

    for (int k0 = 0; k0 < D; k0 += GBK) {
        // load h tile [128 rows][16 k] transposed into hT[k][row]
        #pragma unroll
        for (int q = t; q < 512; q += 256) {
            int r  = q >> 2;            // 0..127
            int c4 = (q & 3) << 2;      // 0,4,8,12
            int grow = row0 + r;
            float4 v = make_float4(0.f, 0.f, 0.f, 0.f);
            if (grow < N_NODES)
                v = *reinterpret_cast<const float4*>(&h[grow * D + k0 + c4]);
            hT[(c4 + 0) * HT_STRIDE + r] = v.x;
            hT[(c4 + 1) * HT_STRIDE + r] = v.y;
            hT[(c4 + 2) * HT_STRIDE + r] = v.z;
            hT[(c4 + 3) * HT_STRIDE + r] = v.w;
        }
        // load W tile [16][128]
        #pragma unroll
        for (int q = t; q < 512; q += 256) {
            int r = q >> 5;             // 0..15
            int c = (q & 31) << 2;
            *reinterpret_cast<float4*>(&wS[r * D + c]) =
                *reinterpret_cast<const float4*>(&W[(k0 + r) * D + c]);
        }
        __syncthreads();

        #pragma unroll
        for (int kk = 0; kk < GBK; kk++) {
            float4 a0 = *reinterpret_cast<const float4*>(&hT[kk * HT_STRIDE + ty * 8]);
            float4 a1 = *reinterpret_cast<const float4*>(&hT[kk * HT_STRIDE + ty * 8 + 4]);
            float4 b0 = *reinterpret_cast<const float4*>(&wS[kk * D + tx * 8]);
            float4 b1 = *reinterpret_cast<const float4*>(&wS[kk * D + tx * 8 + 4]);
            float av[8] = {a0.x, a0.y, a0.z, a0.w, a1.x, a1.y, a1.z, a1.w};
            float bv[8] = {b0.x, b0.y, b0.z, b0.w, b1.x, b1.y, b1.z, b1.w};
            #pragma unroll
            for (int i = 0; i < 8; i++)
                #pragma unroll
                for (int j = 0; j < 8; j++)
                    acc[i][j] += av[i] * bv[j];
        }
        __syncthreads();
    }

    // write z
    #pragma unroll
    for (int i = 0; i < 8; i++) {
        int grow = row0 + ty * 8 + i;
        if (grow < N_NODES) {
            float4 v0 = make_float4(acc[i][0], acc[i][1], acc[i][2], acc[i][3]);
            float4 v1 = make_float4(acc[i][4], acc[i][5], acc[i][6], acc[i][7]);
            *reinterpret_cast<float4*>(&g_z[grow * D + tx * 8])     = v0;
            *reinterpret_cast<float4*>(&g_z[grow * D + tx * 8 + 4]) = v1;
        }
    }

    // fused scores: partial dot of my 8 cols with attn
    float a1v[8], a2v[8];
    #pragma unroll
    for (int j = 0; j < 8; j++) {
        a1v[j] = attn[tx * 8 + j];
        a2v[j] = attn[D + tx * 8 + j];
    }
    #pragma unroll
    for (int i = 0; i < 8; i++) {
        float p1 = 0.f, p2 = 0.f;
        #pragma unroll
        for (int j = 0; j < 8; j++) {
            p1 += acc[i][j] * a1v[j];
            p2 += acc[i][j] * a2v[j];
        }
        sp1[(ty * 8 + i) * 17 + tx] = p1;
        sp2[(ty * 8 + i) * 17 + tx] = p2;
    }
    __syncthreads();
    if (t < 128) {
        int grow = row0 + t;
        if (grow < N_NODES) {
            float s1 = 0.f, s2 = 0.f;
            #pragma unroll
            for (int k = 0; k < 16; k++) {
                s1 += sp1[t * 17 + k];
                s2 += sp2[t * 17 + k];
            }
            g_ssrc[grow] = s1;
            g_sdst[grow] = s2;
        }
    }
}

// ---------------- CSR build ----------------
__global__ void zero_deg_kernel() {
    int i = blockIdx.x * blockDim.x + threadIdx.x;
    if (i < N_NODES) g_deg[i] = 0;
}

__global__ void hist_kernel(const int* __restrict__ dst) {
    int i = blockIdx.x * blockDim.x + threadIdx.x;
    if (i < N_EDGES) atomicAdd(&g_deg[dst[i]], 1);
}

// phase 1: per-block exclusive scan + block sums
__global__ __launch_bounds__(1024) void scan1_kernel() {
    __shared__ int wsum[32];
    int t = threadIdx.x, lane = t & 31, wid = t >> 5;
    int i = blockIdx.x * 1024 + t;
    int v = (i < N_NODES) ? g_deg[i] : 0;
    int x = v;
    #pragma unroll
    for (int o = 1; o < 32; o <<= 1) {
        int y = __shfl_up_sync(0xffffffffu, x, o);
        if (lane >= o) x += y;
    }
    if (lane == 31) wsum[wid] = x;
    __syncthreads();
    if (wid == 0) {
        int s = wsum[lane];
        #pragma unroll
        for (int o = 1; o < 32; o <<= 1) {
            int y = __shfl_up_sync(0xffffffffu, s, o);
            if (lane >= o) s += y;
        }
        wsum[lane] = s;
    }
    __syncthreads();
    int prefix = (wid > 0) ? wsum[wid - 1] : 0;
    int incl = x + prefix;
    if (i < N_NODES) g_off[i] = incl - v;          // block-local exclusive
    if (t == 1023) g_bsum[blockIdx.x] = incl;      // block total
}

// phase 2: scan the 98 block sums (one block, 128 threads)
__global__ __launch_bounds__(128) void scan2_kernel() {
    __shared__ int wsum[4];
    int t = threadIdx.x, lane = t & 31, wid = t >> 5;
    int v = (t < SCAN_BLKS) ? g_bsum[t] : 0;
    int x = v;
    #pragma unroll
    for (int o = 1; o < 32; o <<= 1) {
        int y = __shfl_up_sync(0xffffffffu, x, o);
        if (lane >= o) x += y;
    }
    if (lane == 31) wsum[wid] = x;
    __syncthreads();
    int prefix = 0;
    for (int k = 0; k < wid; k++) prefix += wsum[k];
    int incl = x + prefix;
    if (t < SCAN_BLKS) g_boff[t] = incl - v;
}

// phase 3: add block offsets, init cursors
__global__ void scan3_kernel() {
    int i = blockIdx.x * blockDim.x + threadIdx.x;
    if (i < N_NODES) {
        int v = g_off[i] + g_boff[i >> 10];
        g_off[i] = v;
        g_cur[i] = v;
    }
    if (i == 0) g_off[N_NODES] = N_EDGES;
}

__global__ void scatter_kernel(const int* __restrict__ src, const int* __restrict__ dst) {
    int i = blockIdx.x * blockDim.x + threadIdx.x;
    if (i < N_EDGES) {
        int d = dst[i];
        int p = atomicAdd(&g_cur[d], 1);
        g_csr_src[p] = src[i];
    }
}

// ---------------- single-pass softmax aggregation ----------------
// No max subtraction (|e| <~ 8, exp safe; softmax is shift-invariant).
// out_n = (sum_j w_j z_j) / (sum_j w_j), one warp per node.
__global__ __launch_bounds__(256) void aggregate_kernel(float* __restrict__ out) {
    int wid  = threadIdx.x >> 5;
    int lane = threadIdx.x & 31;
    int n    = blockIdx.x * 8 + wid;
    if (n >= N_NODES) return;

    int start = g_off[n];
    int end   = g_off[n + 1];
    float sd  = g_sdst[n];

    float4 acc = make_float4(0.f, 0.f, 0.f, 0.f);
    float den_l = 0.f;
    int col = lane * 4;

    for (int base = start; base < end; base += 32) {
        int cnt = end - base;
        if (cnt > 32) cnt = 32;
        int s = 0; float w = 0.f;
        if (lane < cnt) {
            s = g_csr_src[base + lane];
            float e = g_ssrc[s] + sd;
            e = (e > 0.f) ? e : NEG_SLOPE * e;
            w = __expf(e);
            den_l += w;
        }
        for (int j = 0; j < cnt; j++) {
            int   sj = __shfl_sync(0xffffffffu, s, j);
            float wj = __shfl_sync(0xffffffffu, w, j);
            float4 zv = *reinterpret_cast<const float4*>(&g_z[sj * D + col]);
            acc.x += wj * zv.x;
            acc.y += wj * zv.y;
            acc.z += wj * zv.z;
            acc.w += wj * zv.w;
        }
    }
    #pragma unroll
    for (int o = 16; o > 0; o >>= 1)
        den_l += __shfl_xor_sync(0xffffffffu, den_l, o);

    float inv = (end > start) ? (1.0f / den_l) : 0.f;
    acc.x *= inv; acc.y *= inv; acc.z *= inv; acc.w *= inv;
    *reinterpret_cast<float4*>(&out[n * D + col]) = acc;
}

// ---------------- launch ----------------
extern "C" void kernel_launch(void* const* d_in, const int* in_sizes, int n_in,
                              void* d_out, int out_size) {
    const float* h    = (const float*)d_in[0];
    const float* W    = (const float*)d_in[1];
    const float* attn = (const float*)d_in[2];
    const int* esrc   = (const int*)d_in[3];
    const int* edst   = (const int*)d_in[4];
    float* out        = (float*)d_out;

    (void)in_sizes; (void)n_in; (void)out_size;

    gemm_scores_kernel<<<(N_NODES + GBM - 1) / GBM, 256>>>(h, W, attn);
    zero_deg_kernel<<<(N_NODES + 255) / 256, 256>>>();
    hist_kernel<<<(N_EDGES + 255) / 256, 256>>>(edst);
    scan1_kernel<<<SCAN_BLKS, 1024>>>();
    scan2_kernel<<<1, 128>>>();
    scan3_kernel<<<(N_NODES + 255) / 256, 256>>>();
    scatter_kernel<<<(N_EDGES + 255) / 256, 256>>>(esrc, edst);
    aggregate_kernel<<<(N_NODES + 7) / 8, 256>>>(out);
}

// round 5
// speedup vs baseline: 1.7294x; 1.1189x over previous
#include <cuda_runtime.h>
#include <cuda_fp16.h>
#include <math.h>
#include <stdint.h>

#define N_NODES 100000
#define N_EDGES 1600000
#define D 128
#define NEG_SLOPE 0.01f
#define SCAN_BLKS ((N_NODES + 1023) / 1024)   // 98

// ---------------- scratch (no allocations allowed) ----------------
__device__ __half2 g_zh[N_NODES * (D / 2)];   // 25.6 MB, z in fp16
__device__ float g_ssrc[N_NODES];
__device__ float g_sdst[N_NODES];
__device__ int   g_deg[N_NODES];
__device__ int   g_off[N_NODES + 1];
__device__ int   g_cur[N_NODES];
__device__ int   g_csr_src[N_EDGES];
__device__ int   g_bsum[128];
__device__ int   g_boff[128];

// ---------------- GEMM z = h@W with fused scores, fp16 z output ----------------
#define GBM 128
#define GBK 16
#define HT_STRIDE 132
#define SMEM_FLOATS 4352

__global__ __launch_bounds__(256) void gemm_scores_kernel(const float* __restrict__ h,
                                                          const float* __restrict__ W,
                                                          const float* __restrict__ attn) {
    __shared__ float smem[SMEM_FLOATS];
    float* hT = smem;                       // [GBK][HT_STRIDE]
    float* wS = smem + GBK * HT_STRIDE;     // [GBK][128]
    float* sp1 = smem;                      // [128][17] (reused)
    float* sp2 = smem + 128 * 17;

    const int t  = threadIdx.x;
    const int tx = t & 15;
    const int ty = t >> 4;
    const int row0 = blockIdx.x * GBM;

    float acc[8][8];
    #pragma unroll
    for (int i = 0; i < 8; i++)
        #pragma unroll
        for (int j = 0; j < 8; j++) acc[i][j] = 0.0f;

    for (int k0 = 0; k0 < D; k0 += GBK) {
        #pragma unroll
        for (int q = t; q < 512; q += 256) {
            int r  = q >> 2;
            int c4 = (q & 3) << 2;
            int grow = row0 + r;
            float4 v = make_float4(0.f, 0.f, 0.f, 0.f);
            if (grow < N_NODES)
                v = *reinterpret_cast<const float4*>(&h[grow * D + k0 + c4]);
            hT[(c4 + 0) * HT_STRIDE + r] = v.x;
            hT[(c4 + 1) * HT_STRIDE + r] = v.y;
            hT[(c4 + 2) * HT_STRIDE + r] = v.z;
            hT[(c4 + 3) * HT_STRIDE + r] = v.w;
        }
        #pragma unroll
        for (int q = t; q < 512; q += 256) {
            int r = q >> 5;
            int c = (q & 31) << 2;
            *reinterpret_cast<float4*>(&wS[r * D + c]) =
                *reinterpret_cast<const float4*>(&W[(k0 + r) * D + c]);
        }
        __syncthreads();

        #pragma unroll
        for (int kk = 0; kk < GBK; kk++) {
            float4 a0 = *reinterpret_cast<const float4*>(&hT[kk * HT_STRIDE + ty * 8]);
            float4 a1 = *reinterpret_cast<const float4*>(&hT[kk * HT_STRIDE + ty * 8 + 4]);
            float4 b0 = *reinterpret_cast<const float4*>(&wS[kk * D + tx * 8]);
            float4 b1 = *reinterpret_cast<const float4*>(&wS[kk * D + tx * 8 + 4]);
            float av[8] = {a0.x, a0.y, a0.z, a0.w, a1.x, a1.y, a1.z, a1.w};
            float bv[8] = {b0.x, b0.y, b0.z, b0.w, b1.x, b1.y, b1.z, b1.w};
            #pragma unroll
            for (int i = 0; i < 8; i++)
                #pragma unroll
                for (int j = 0; j < 8; j++)
                    acc[i][j] += av[i] * bv[j];
        }
        __syncthreads();
    }

    // write z as fp16 (8 halves = 16B per thread-row)
    #pragma unroll
    for (int i = 0; i < 8; i++) {
        int grow = row0 + ty * 8 + i;
        if (grow < N_NODES) {
            __half2 hv[4];
            #pragma unroll
            for (int j = 0; j < 4; j++)
                hv[j] = __floats2half2_rn(acc[i][2 * j], acc[i][2 * j + 1]);
            *reinterpret_cast<uint4*>(&g_zh[grow * (D / 2) + tx * 4]) =
                *reinterpret_cast<uint4*>(hv);
        }
    }

    // fused scores (fp32)
    float a1v[8], a2v[8];
    #pragma unroll
    for (int j = 0; j < 8; j++) {
        a1v[j] = attn[tx * 8 + j];
        a2v[j] = attn[D + tx * 8 + j];
    }
    #pragma unroll
    for (int i = 0; i < 8; i++) {
        float p1 = 0.f, p2 = 0.f;
        #pragma unroll
        for (int j = 0; j < 8; j++) {
            p1 += acc[i][j] * a1v[j];
            p2 += acc[i][j] * a2v[j];
        }
        sp1[(ty * 8 + i) * 17 + tx] = p1;
        sp2[(ty * 8 + i) * 17 + tx] = p2;
    }
    __syncthreads();
    if (t < 128) {
        int grow = row0 + t;
        if (grow < N_NODES) {
            float s1 = 0.f, s2 = 0.f;
            #pragma unroll
            for (int k = 0; k < 16; k++) {
                s1 += sp1[t * 17 + k];
                s2 += sp2[t * 17 + k];
            }
            g_ssrc[grow] = s1;
            g_sdst[grow] = s2;
        }
    }
}

// ---------------- CSR build ----------------
__global__ void zero_deg_kernel() {
    int i = blockIdx.x * blockDim.x + threadIdx.x;
    if (i < N_NODES) g_deg[i] = 0;
}

__global__ void hist_kernel(const int* __restrict__ dst) {
    int i = blockIdx.x * blockDim.x + threadIdx.x;
    if (i < N_EDGES) atomicAdd(&g_deg[dst[i]], 1);
}

__global__ __launch_bounds__(1024) void scan1_kernel() {
    __shared__ int wsum[32];
    int t = threadIdx.x, lane = t & 31, wid = t >> 5;
    int i = blockIdx.x * 1024 + t;
    int v = (i < N_NODES) ? g_deg[i] : 0;
    int x = v;
    #pragma unroll
    for (int o = 1; o < 32; o <<= 1) {
        int y = __shfl_up_sync(0xffffffffu, x, o);
        if (lane >= o) x += y;
    }
    if (lane == 31) wsum[wid] = x;
    __syncthreads();
    if (wid == 0) {
        int s = wsum[lane];
        #pragma unroll
        for (int o = 1; o < 32; o <<= 1) {
            int y = __shfl_up_sync(0xffffffffu, s, o);
            if (lane >= o) s += y;
        }
        wsum[lane] = s;
    }
    __syncthreads();
    int prefix = (wid > 0) ? wsum[wid - 1] : 0;
    int incl = x + prefix;
    if (i < N_NODES) g_off[i] = incl - v;
    if (t == 1023) g_bsum[blockIdx.x] = incl;
}

__global__ __launch_bounds__(128) void scan2_kernel() {
    __shared__ int wsum[4];
    int t = threadIdx.x, lane = t & 31, wid = t >> 5;
    int v = (t < SCAN_BLKS) ? g_bsum[t] : 0;
    int x = v;
    #pragma unroll
    for (int o = 1; o < 32; o <<= 1) {
        int y = __shfl_up_sync(0xffffffffu, x, o);
        if (lane >= o) x += y;
    }
    if (lane == 31) wsum[wid] = x;
    __syncthreads();
    int prefix = 0;
    for (int k = 0; k < wid; k++) prefix += wsum[k];
    int incl = x + prefix;
    if (t < SCAN_BLKS) g_boff[t] = incl - v;
}

__global__ void scan3_kernel() {
    int i = blockIdx.x * blockDim.x + threadIdx.x;
    if (i < N_NODES) {
        int v = g_off[i] + g_boff[i >> 10];
        g_off[i] = v;
        g_cur[i] = v;
    }
    if (i == 0) g_off[N_NODES] = N_EDGES;
}

__global__ void scatter_kernel(const int* __restrict__ src, const int* __restrict__ dst) {
    int i = blockIdx.x * blockDim.x + threadIdx.x;
    if (i < N_EDGES) {
        int d = dst[i];
        int p = atomicAdd(&g_cur[d], 1);
        g_csr_src[p] = src[i];
    }
}

// ---------------- single-pass softmax aggregation (fp16 z gather) ----------------
// out_n = (sum_j w_j z_j) / (sum_j w_j); one warp per node; lane owns 4 cols.
__global__ __launch_bounds__(256) void aggregate_kernel(float* __restrict__ out) {
    int wid  = threadIdx.x >> 5;
    int lane = threadIdx.x & 31;
    int n    = blockIdx.x * 8 + wid;
    if (n >= N_NODES) return;

    int start = g_off[n];
    int end   = g_off[n + 1];
    float sd  = g_sdst[n];

    float4 acc = make_float4(0.f, 0.f, 0.f, 0.f);
    float den_l = 0.f;
    const int h2col = lane * 2;            // 2 half2 = 4 floats per lane

    for (int base = start; base < end; base += 32) {
        int cnt = end - base;
        if (cnt > 32) cnt = 32;
        int s = 0; float w = 0.f;
        if (lane < cnt) {
            s = g_csr_src[base + lane];
            float e = g_ssrc[s] + sd;
            e = (e > 0.f) ? e : NEG_SLOPE * e;
            w = __expf(e);
            den_l += w;
        }
        #pragma unroll 4
        for (int j = 0; j < cnt; j++) {
            int   sj = __shfl_sync(0xffffffffu, s, j);
            float wj = __shfl_sync(0xffffffffu, w, j);
            uint2 raw = *reinterpret_cast<const uint2*>(&g_zh[sj * (D / 2) + h2col]);
            float2 z0 = __half22float2(*reinterpret_cast<__half2*>(&raw.x));
            float2 z1 = __half22float2(*reinterpret_cast<__half2*>(&raw.y));
            acc.x += wj * z0.x;
            acc.y += wj * z0.y;
            acc.z += wj * z1.x;
            acc.w += wj * z1.y;
        }
    }
    #pragma unroll
    for (int o = 16; o > 0; o >>= 1)
        den_l += __shfl_xor_sync(0xffffffffu, den_l, o);

    float inv = (end > start) ? (1.0f / den_l) : 0.f;
    acc.x *= inv; acc.y *= inv; acc.z *= inv; acc.w *= inv;
    *reinterpret_cast<float4*>(&out[n * D + lane * 4]) = acc;
}

// ---------------- launch ----------------
extern "C" void kernel_launch(void* const* d_in, const int* in_sizes, int n_in,
                              void* d_out, int out_size) {
    const float* h    = (const float*)d_in[0];
    const float* W    = (const float*)d_in[1];
    const float* attn = (const float*)d_in[2];
    const int* esrc   = (const int*)d_in[3];
    const int* edst   = (const int*)d_in[4];
    float* out        = (float*)d_out;

    (void)in_sizes; (void)n_in; (void)out_size;

    gemm_scores_kernel<<<(N_NODES + GBM - 1) / GBM, 256>>>(h, W, attn);
    zero_deg_kernel<<<(N_NODES + 255) / 256, 256>>>();
    hist_kernel<<<(N_EDGES + 255) / 256, 256>>>(edst);
    scan1_kernel<<<SCAN_BLKS, 1024>>>();
    scan2_kernel<<<1, 128>>>();
    scan3_kernel<<<(N_NODES + 255) / 256, 256>>>();
    scatter_kernel<<<(N_EDGES + 255) / 256, 256>>>(esrc, edst);
    aggregate_kernel<<<(N_NODES + 7) / 8, 256>>>(out);
}